// round 4
// baseline (speedup 1.0000x reference)
#include <cuda_runtime.h>
#include <cstdint>
#include <cstddef>

#define CH 128
#define MAXN 131072
#define GN_EPS 1e-5f

// ---------------- scratch (static device arrays; no runtime alloc) -------------
__device__ float g_feat[(size_t)MAXN * CH];
__device__ float g_idn [(size_t)MAXN * CH];
__device__ float g_tmp [(size_t)MAXN * CH];
__device__ float g_msg [(size_t)MAXN * CH];

// ---------------- packed f32x2 helpers (sm_103a) --------------------------------
#define PACK2(d, x) asm("mov.b64 %0, {%1, %1};" : "=l"(d) : "r"(__float_as_uint(x)))
#define FMA2(d, a, b) asm("fma.rn.f32x2 %0, %1, %2, %0;" : "+l"(d) : "l"(a), "l"(b))

// ---------------- GEMM: C[n,128] = A[n,128] @ W[128,128] ------------------------
// BM=64 rows/CTA, full K=128 and N=128 resident in smem.
// 256 threads: 16x16 grid, each thread 4 rows x 8 cols (as 4 f32x2 pairs).
__global__ __launch_bounds__(256) void gemm128(
    const float* __restrict__ A, const float* __restrict__ W,
    float* __restrict__ C, int nrows)
{
    extern __shared__ float sm[];
    float* As = sm;               // [128][64]  k-major (transposed)
    float* Ws = sm + 128 * 64;    // [128][128]
    const int tid = threadIdx.x;
    const int r0  = blockIdx.x * 64;

    // Load A tile transposed: thread f -> row r=f&63 (conflict-free STS), kq=f>>6
#pragma unroll
    for (int j = 0; j < 8; j++) {
        int f  = tid + 256 * j;
        int r  = f & 63;
        int kq = f >> 6;
        int row = r0 + r;
        float4 a = make_float4(0.f, 0.f, 0.f, 0.f);
        if (row < nrows) a = *(const float4*)(A + (size_t)row * CH + kq * 4);
        As[(kq * 4 + 0) * 64 + r] = a.x;
        As[(kq * 4 + 1) * 64 + r] = a.y;
        As[(kq * 4 + 2) * 64 + r] = a.z;
        As[(kq * 4 + 3) * 64 + r] = a.w;
    }
    // Load full W (coalesced float4 copy)
#pragma unroll
    for (int j = 0; j < 16; j++) {
        int f = tid + 256 * j;
        *(float4*)(Ws + f * 4) = *(const float4*)(W + f * 4);
    }
    __syncthreads();

    const int trow = tid >> 4;   // 0..15 -> rows trow*4..+3
    const int tcol = tid & 15;   // 0..15 -> cols tcol*8..+7

    unsigned long long acc[4][4];
#pragma unroll
    for (int m = 0; m < 4; m++)
#pragma unroll
        for (int p = 0; p < 4; p++) acc[m][p] = 0ULL;

    const float* Ap = As + trow * 4;
    const float* Wp = Ws + tcol * 8;

#pragma unroll 4
    for (int k = 0; k < 128; k++) {
        float4 av = *(const float4*)(Ap + k * 64);
        ulonglong2 w01 = *(const ulonglong2*)(Wp + k * CH);       // cols +0..3
        ulonglong2 w23 = *(const ulonglong2*)(Wp + k * CH + 4);   // cols +4..7
        unsigned long long ap;
        PACK2(ap, av.x);
        FMA2(acc[0][0], ap, w01.x); FMA2(acc[0][1], ap, w01.y);
        FMA2(acc[0][2], ap, w23.x); FMA2(acc[0][3], ap, w23.y);
        PACK2(ap, av.y);
        FMA2(acc[1][0], ap, w01.x); FMA2(acc[1][1], ap, w01.y);
        FMA2(acc[1][2], ap, w23.x); FMA2(acc[1][3], ap, w23.y);
        PACK2(ap, av.z);
        FMA2(acc[2][0], ap, w01.x); FMA2(acc[2][1], ap, w01.y);
        FMA2(acc[2][2], ap, w23.x); FMA2(acc[2][3], ap, w23.y);
        PACK2(ap, av.w);
        FMA2(acc[3][0], ap, w01.x); FMA2(acc[3][1], ap, w01.y);
        FMA2(acc[3][2], ap, w23.x); FMA2(acc[3][3], ap, w23.y);
    }

#pragma unroll
    for (int m = 0; m < 4; m++) {
        int row = r0 + trow * 4 + m;
        if (row < nrows) {
            ulonglong2* cp = (ulonglong2*)(C + (size_t)row * CH + tcol * 8);
            cp[0] = make_ulonglong2(acc[m][0], acc[m][1]);
            cp[1] = make_ulonglong2(acc[m][2], acc[m][3]);
        }
    }
}

// ---------------- scatter: T[u,:] += M[v,:]  (one warp per edge) ----------------
__global__ void scatter_add(const float* __restrict__ M, float* __restrict__ T,
                            const int* __restrict__ U, const int* __restrict__ V,
                            int ne)
{
    int gw   = (int)((blockIdx.x * (unsigned)blockDim.x + threadIdx.x) >> 5);
    int lane = threadIdx.x & 31;
    if (gw >= ne) return;
    int u = __ldg(U + gw);
    int v = __ldg(V + gw);
    float4 val = *(const float4*)(M + (size_t)v * CH + lane * 4);
    float* dst = T + (size_t)u * CH + lane * 4;
    atomicAdd(dst + 0, val.x);
    atomicAdd(dst + 1, val.y);
    atomicAdd(dst + 2, val.z);
    atomicAdd(dst + 3, val.w);
}

// ---------------- GroupNorm building blocks (one warp per row) ------------------
__device__ __forceinline__ void warp_red2(float& a, float& b)
{
#pragma unroll
    for (int o = 16; o; o >>= 1) {
        a += __shfl_xor_sync(0xffffffffu, a, o);
        b += __shfl_xor_sync(0xffffffffu, b, o);
    }
}

// Y = relu(GN(X)*g + b)   (in-place safe)
__global__ void gn_relu_k(const float* __restrict__ X, const float* __restrict__ G,
                          const float* __restrict__ Bv, float* __restrict__ Y, int n)
{
    int row  = (int)((blockIdx.x * (unsigned)blockDim.x + threadIdx.x) >> 5);
    int lane = threadIdx.x & 31;
    if (row >= n) return;
    float4 x = *(const float4*)(X + (size_t)row * CH + lane * 4);
    float s = x.x + x.y + x.z + x.w;
    float q = x.x * x.x + x.y * x.y + x.z * x.z + x.w * x.w;
    warp_red2(s, q);
    float mu = s * (1.f / CH);
    float rs = rsqrtf(q * (1.f / CH) - mu * mu + GN_EPS);
    float4 g = *(const float4*)(G + lane * 4);
    float4 b = *(const float4*)(Bv + lane * 4);
    float4 y;
    y.x = fmaxf((x.x - mu) * rs * g.x + b.x, 0.f);
    y.y = fmaxf((x.y - mu) * rs * g.y + b.y, 0.f);
    y.z = fmaxf((x.z - mu) * rs * g.z + b.z, 0.f);
    y.w = fmaxf((x.w - mu) * rs * g.w + b.w, 0.f);
    *(float4*)(Y + (size_t)row * CH + lane * 4) = y;
}

// F = ID = relu(GN(X)*g + b + ID); optionally also write OUT
__global__ void gn_res_k(const float* __restrict__ X, const float* __restrict__ G,
                         const float* __restrict__ Bv, float* __restrict__ ID,
                         float* __restrict__ F, float* __restrict__ OUT, int n)
{
    int row  = (int)((blockIdx.x * (unsigned)blockDim.x + threadIdx.x) >> 5);
    int lane = threadIdx.x & 31;
    if (row >= n) return;
    size_t off = (size_t)row * CH + lane * 4;
    float4 x = *(const float4*)(X + off);
    float s = x.x + x.y + x.z + x.w;
    float q = x.x * x.x + x.y * x.y + x.z * x.z + x.w * x.w;
    warp_red2(s, q);
    float mu = s * (1.f / CH);
    float rs = rsqrtf(q * (1.f / CH) - mu * mu + GN_EPS);
    float4 g  = *(const float4*)(G + lane * 4);
    float4 b  = *(const float4*)(Bv + lane * 4);
    float4 id = *(const float4*)(ID + off);
    float4 y;
    y.x = fmaxf((x.x - mu) * rs * g.x + b.x + id.x, 0.f);
    y.y = fmaxf((x.y - mu) * rs * g.y + b.y + id.y, 0.f);
    y.z = fmaxf((x.z - mu) * rs * g.z + b.z + id.z, 0.f);
    y.w = fmaxf((x.w - mu) * rs * g.w + b.w + id.w, 0.f);
    *(float4*)(F + off) = y;
    *(float4*)(ID + off) = y;
    if (OUT) *(float4*)(OUT + off) = y;
}

// X1 = X2 = relu(GN(X1)*g1+b1 + GN(X2)*g2+b2)   (input-stage combine)
__global__ void gn_combine_k(float* __restrict__ X1, float* __restrict__ X2,
                             const float* __restrict__ G1, const float* __restrict__ B1,
                             const float* __restrict__ G2, const float* __restrict__ B2,
                             int n)
{
    int row  = (int)((blockIdx.x * (unsigned)blockDim.x + threadIdx.x) >> 5);
    int lane = threadIdx.x & 31;
    if (row >= n) return;
    size_t off = (size_t)row * CH + lane * 4;
    float4 a = *(const float4*)(X1 + off);
    float4 c = *(const float4*)(X2 + off);
    float s1 = a.x + a.y + a.z + a.w;
    float q1 = a.x * a.x + a.y * a.y + a.z * a.z + a.w * a.w;
    float s2 = c.x + c.y + c.z + c.w;
    float q2 = c.x * c.x + c.y * c.y + c.z * c.z + c.w * c.w;
    warp_red2(s1, q1);
    warp_red2(s2, q2);
    float mu1 = s1 * (1.f / CH);
    float rs1 = rsqrtf(q1 * (1.f / CH) - mu1 * mu1 + GN_EPS);
    float mu2 = s2 * (1.f / CH);
    float rs2 = rsqrtf(q2 * (1.f / CH) - mu2 * mu2 + GN_EPS);
    float4 g1 = *(const float4*)(G1 + lane * 4);
    float4 b1 = *(const float4*)(B1 + lane * 4);
    float4 g2 = *(const float4*)(G2 + lane * 4);
    float4 b2 = *(const float4*)(B2 + lane * 4);
    float4 y;
    y.x = fmaxf((a.x - mu1) * rs1 * g1.x + b1.x + (c.x - mu2) * rs2 * g2.x + b2.x, 0.f);
    y.y = fmaxf((a.y - mu1) * rs1 * g1.y + b1.y + (c.y - mu2) * rs2 * g2.y + b2.y, 0.f);
    y.z = fmaxf((a.z - mu1) * rs1 * g1.z + b1.z + (c.z - mu2) * rs2 * g2.z + b2.z, 0.f);
    y.w = fmaxf((a.w - mu1) * rs1 * g1.w + b1.w + (c.w - mu2) * rs2 * g2.w + b2.w, 0.f);
    *(float4*)(X1 + off) = y;
    *(float4*)(X2 + off) = y;
}

// H1 = relu(ctrs@cw0 + cb0), H2 = relu(feats@fw0 + fb0)  (K=2 first layers)
__global__ void input_mlp0(const float* __restrict__ ctrs, const float* __restrict__ feats,
                           const float* __restrict__ cw0, const float* __restrict__ cb0,
                           const float* __restrict__ fw0, const float* __restrict__ fb0,
                           float* __restrict__ H1, float* __restrict__ H2, int n)
{
    int row  = (int)((blockIdx.x * (unsigned)blockDim.x + threadIdx.x) >> 5);
    int lane = threadIdx.x & 31;
    if (row >= n) return;
    float c0 = __ldg(ctrs + (size_t)row * 2 + 0);
    float c1 = __ldg(ctrs + (size_t)row * 2 + 1);
    float e0 = __ldg(feats + (size_t)row * 2 + 0);
    float e1 = __ldg(feats + (size_t)row * 2 + 1);
    size_t off = (size_t)row * CH + lane * 4;

    float4 wa = *(const float4*)(cw0 + lane * 4);
    float4 wb = *(const float4*)(cw0 + CH + lane * 4);
    float4 bb = *(const float4*)(cb0 + lane * 4);
    float4 h;
    h.x = fmaxf(c0 * wa.x + c1 * wb.x + bb.x, 0.f);
    h.y = fmaxf(c0 * wa.y + c1 * wb.y + bb.y, 0.f);
    h.z = fmaxf(c0 * wa.z + c1 * wb.z + bb.z, 0.f);
    h.w = fmaxf(c0 * wa.w + c1 * wb.w + bb.w, 0.f);
    *(float4*)(H1 + off) = h;

    wa = *(const float4*)(fw0 + lane * 4);
    wb = *(const float4*)(fw0 + CH + lane * 4);
    bb = *(const float4*)(fb0 + lane * 4);
    h.x = fmaxf(e0 * wa.x + e1 * wb.x + bb.x, 0.f);
    h.y = fmaxf(e0 * wa.y + e1 * wb.y + bb.y, 0.f);
    h.z = fmaxf(e0 * wa.z + e1 * wb.z + bb.z, 0.f);
    h.w = fmaxf(e0 * wa.w + e1 * wb.w + bb.w, 0.f);
    *(float4*)(H2 + off) = h;
}

// ---------------- orchestration -------------------------------------------------
extern "C" void kernel_launch(void* const* d_in, const int* in_sizes, int n_in,
                              void* d_out, int out_size)
{
    const float* ctrs   = (const float*)d_in[0];
    const float* feats  = (const float*)d_in[1];
    const int*   pre_u  = (const int*)d_in[2];
    const int*   pre_v  = (const int*)d_in[3];
    const int*   suc_u  = (const int*)d_in[4];
    const int*   suc_v  = (const int*)d_in[5];
    const int*   left_u = (const int*)d_in[6];
    const int*   left_v = (const int*)d_in[7];
    const int*   right_u= (const int*)d_in[8];
    const int*   right_v= (const int*)d_in[9];
    const float* ic_w0  = (const float*)d_in[10];
    const float* ic_b0  = (const float*)d_in[11];
    const float* ic_w1  = (const float*)d_in[12];
    const float* ic_g   = (const float*)d_in[13];
    const float* ic_bt  = (const float*)d_in[14];
    const float* if_w0  = (const float*)d_in[15];
    const float* if_b0  = (const float*)d_in[16];
    const float* if_w1  = (const float*)d_in[17];
    const float* if_g   = (const float*)d_in[18];
    const float* if_bt  = (const float*)d_in[19];
    const float* ctr_w  = (const float*)d_in[20];
    const float* pre_w  = (const float*)d_in[21];
    const float* suc_w  = (const float*)d_in[22];
    const float* left_w = (const float*)d_in[23];
    const float* right_w= (const float*)d_in[24];
    const float* norm_g = (const float*)d_in[25];
    const float* norm_b = (const float*)d_in[26];
    const float* ctr2_w = (const float*)d_in[27];
    const float* ctr2_g = (const float*)d_in[28];
    const float* ctr2_b = (const float*)d_in[29];

    const int N   = in_sizes[0] / 2;
    const int EL  = in_sizes[6];
    const int BCC = in_sizes[20];              // B*C*C
    const int nB  = BCC / (CH * CH);
    const int S   = in_sizes[21] / BCC;        // (B*S*C*C)/(B*C*C)
    const int E   = in_sizes[2] / S;

    float *feat, *idn, *tmp, *msg;
    cudaGetSymbolAddress((void**)&feat, g_feat);
    cudaGetSymbolAddress((void**)&idn,  g_idn);
    cudaGetSymbolAddress((void**)&tmp,  g_tmp);
    cudaGetSymbolAddress((void**)&msg,  g_msg);

    const int GEMM_SMEM = (128 * 64 + 128 * 128) * (int)sizeof(float);  // 96 KB
    cudaFuncSetAttribute(gemm128, cudaFuncAttributeMaxDynamicSharedMemorySize, GEMM_SMEM);

    const int gGrid  = (N + 63) / 64;
    const int rwGrid = (N * 32 + 255) / 256;           // one warp per row
    const int eGrid  = (E * 32 + 255) / 256;           // one warp per edge
    const int elGrid = (EL * 32 + 255) / 256;

    // ---- input stage: feat = identity = relu(GN(h1@ic_w1) + GN(h2@if_w1)) ----
    input_mlp0<<<rwGrid, 256>>>(ctrs, feats, ic_w0, ic_b0, if_w0, if_b0, tmp, msg, N);
    gemm128<<<gGrid, 256, GEMM_SMEM>>>(tmp, ic_w1, feat, N);
    gemm128<<<gGrid, 256, GEMM_SMEM>>>(msg, if_w1, idn, N);
    gn_combine_k<<<rwGrid, 256>>>(feat, idn, ic_g, ic_bt, if_g, if_bt, N);

    // ---- fusion blocks ----
    for (int i = 0; i < nB; i++) {
        const size_t cc = (size_t)CH * CH;
        gemm128<<<gGrid, 256, GEMM_SMEM>>>(feat, ctr_w + (size_t)i * cc, tmp, N);

        for (int s = 0; s < S; s++) {
            gemm128<<<gGrid, 256, GEMM_SMEM>>>(feat, pre_w + ((size_t)i * S + s) * cc, msg, N);
            scatter_add<<<eGrid, 256>>>(msg, tmp, pre_u + (size_t)s * E, pre_v + (size_t)s * E, E);
        }
        for (int s = 0; s < S; s++) {
            gemm128<<<gGrid, 256, GEMM_SMEM>>>(feat, suc_w + ((size_t)i * S + s) * cc, msg, N);
            scatter_add<<<eGrid, 256>>>(msg, tmp, suc_u + (size_t)s * E, suc_v + (size_t)s * E, E);
        }
        gemm128<<<gGrid, 256, GEMM_SMEM>>>(feat, left_w + (size_t)i * cc, msg, N);
        scatter_add<<<elGrid, 256>>>(msg, tmp, left_u, left_v, EL);
        gemm128<<<gGrid, 256, GEMM_SMEM>>>(feat, right_w + (size_t)i * cc, msg, N);
        scatter_add<<<elGrid, 256>>>(msg, tmp, right_u, right_v, EL);

        // feat' = relu(GN(temp))  (in place on tmp), then ctr2 GEMM, then GN+residual
        gn_relu_k<<<rwGrid, 256>>>(tmp, norm_g + (size_t)i * CH, norm_b + (size_t)i * CH, tmp, N);
        gemm128<<<gGrid, 256, GEMM_SMEM>>>(tmp, ctr2_w + (size_t)i * cc, msg, N);
        gn_res_k<<<rwGrid, 256>>>(msg, ctr2_g + (size_t)i * CH, ctr2_b + (size_t)i * CH,
                                  idn, feat,
                                  (i == nB - 1) ? (float*)d_out : (float*)nullptr, N);
    }
}

// round 7
// speedup vs baseline: 2.7981x; 2.7981x over previous
#include <cuda_runtime.h>
#include <cuda_bf16.h>
#include <cstdint>
#include <cstddef>

#define CH 128
#define MAXN 131072
#define MAXS 6
#define GN_EPS 1e-5f

// ---------------- static scratch (no runtime alloc) ----------------------------
__device__ float g_idn [(size_t)MAXN * CH];
__device__ float g_tmp [(size_t)MAXN * CH];
__device__ float g_msg [(size_t)2 * MAXS * MAXN * CH];
__device__ __nv_bfloat16 g_a0h[(size_t)MAXN * CH];
__device__ __nv_bfloat16 g_a0l[(size_t)MAXN * CH];
__device__ __nv_bfloat16 g_a1h[(size_t)MAXN * CH];
__device__ __nv_bfloat16 g_a1l[(size_t)MAXN * CH];
#define MAXW 128
__device__ __nv_bfloat16 g_whi[(size_t)MAXW * CH * CH];
__device__ __nv_bfloat16 g_wlo[(size_t)MAXW * CH * CH];

// ---------------- helpers -------------------------------------------------------
__device__ __forceinline__ uint32_t smem_u32(const void* p) {
    uint32_t a;
    asm("{ .reg .u64 t; cvta.to.shared.u64 t, %1; cvt.u32.u64 %0, t; }" : "=r"(a) : "l"(p));
    return a;
}

#define LDSM4(d0, d1, d2, d3, addr) \
    asm volatile("ldmatrix.sync.aligned.m8n8.x4.shared.b16 {%0,%1,%2,%3}, [%4];" \
                 : "=r"(d0), "=r"(d1), "=r"(d2), "=r"(d3) : "r"(addr))

#define MMA16816(c, a, b0, b1) \
    asm volatile("mma.sync.aligned.m16n8k16.row.col.f32.bf16.bf16.f32 " \
                 "{%0,%1,%2,%3}, {%4,%5,%6,%7}, {%8,%9}, {%0,%1,%2,%3};" \
                 : "+f"((c)[0]), "+f"((c)[1]), "+f"((c)[2]), "+f"((c)[3]) \
                 : "r"((a)[0]), "r"((a)[1]), "r"((a)[2]), "r"((a)[3]), "r"(b0), "r"(b1))

// ---------------- mma.sync split-bf16 GEMM --------------------------------------
// C[bY][n,128] = (Ahi+Alo)[n,128] @ (Whi+Wlo)[bY]^T ; W stored [N=128][K=128] bf16.
#define PADK 136                           // 128 + 8 bf16 pad -> 272B rows, 16B aligned
#define TILE_B ((size_t)128 * PADK * 2)    // 34816 bytes per matrix tile
#define GEMM_SMEM (4 * 34816)              // 139264 bytes

__global__ __launch_bounds__(256, 1)
void gemm_tc(const __nv_bfloat16* __restrict__ Ahi, const __nv_bfloat16* __restrict__ Alo,
             const __nv_bfloat16* __restrict__ Whi, const __nv_bfloat16* __restrict__ Wlo,
             float* __restrict__ C, int nrows)
{
    extern __shared__ __nv_bfloat16 sm[];
    __nv_bfloat16* sAh = sm;                    // [128][PADK]
    __nv_bfloat16* sAl = sm + 128 * PADK;
    __nv_bfloat16* sWh = sm + 2 * 128 * PADK;
    __nv_bfloat16* sWl = sm + 3 * 128 * PADK;

    const int tid  = threadIdx.x;
    const int lane = tid & 31;
    const int wid  = tid >> 5;
    const int wm   = wid >> 1;    // 0..3 -> rows wm*32
    const int wn   = wid & 1;     // 0..1 -> cols wn*64
    const int r0   = blockIdx.x * 128;
    const size_t woff = (size_t)blockIdx.y * (CH * CH);
    float* Cb = C + (size_t)blockIdx.y * (size_t)nrows * CH;

    const uint4* gAh = (const uint4*)(Ahi + (size_t)r0 * CH);
    const uint4* gAl = (const uint4*)(Alo + (size_t)r0 * CH);
    const uint4* gWh = (const uint4*)(Whi + woff);
    const uint4* gWl = (const uint4*)(Wlo + woff);
    const uint4 z4 = make_uint4(0, 0, 0, 0);

#pragma unroll
    for (int it = 0; it < 8; it++) {
        int ch  = tid + it * 256;          // 0..2047
        int row = ch >> 4, c = ch & 15;
        size_t doff = (size_t)row * PADK + c * 8;
        bool ok = (r0 + row) < nrows;
        *(uint4*)(sAh + doff) = ok ? gAh[ch] : z4;
        *(uint4*)(sAl + doff) = ok ? gAl[ch] : z4;
        *(uint4*)(sWh + doff) = gWh[ch];
        *(uint4*)(sWl + doff) = gWl[ch];
    }
    __syncthreads();

    const uint32_t sbase = smem_u32(sm);
    // A ldmatrix.x4 lane address: row = wm*32 + mt*16 + (lane&15), col = (lane>>4)*8 + k0
    const uint32_t aAddr = sbase +
        (uint32_t)(((wm * 32 + (lane & 15)) * PADK + (lane >> 4) * 8) * 2);
    // B ldmatrix.x4 lane address: n = wn*64 + nt*16 + (lane&7) + ((lane>>4)<<3),
    //                             k = ((lane>>3)&1)*8 + k0
    const uint32_t bAddr = sbase + (uint32_t)(2 * 128 * PADK * 2) +
        (uint32_t)(((wn * 64 + (lane & 7) + ((lane >> 4) << 3)) * PADK +
                    ((lane >> 3) & 1) * 8) * 2);

    float acc[2][8][4];
#pragma unroll
    for (int mt = 0; mt < 2; mt++)
#pragma unroll
        for (int f = 0; f < 8; f++)
#pragma unroll
            for (int i = 0; i < 4; i++) acc[mt][f][i] = 0.f;

#pragma unroll
    for (int term = 0; term < 3; term++) {
        const uint32_t aOff = (term == 1) ? (uint32_t)TILE_B : 0u;  // Alo for term 1
        const uint32_t wOff = (term == 2) ? (uint32_t)TILE_B : 0u;  // Wlo for term 2
#pragma unroll
        for (int ks = 0; ks < 8; ks++) {
            const uint32_t kb = ks * 32;            // k0 * 2 bytes
            uint32_t a0[4], a1[4];
            LDSM4(a0[0], a0[1], a0[2], a0[3], aAddr + aOff + kb);
            LDSM4(a1[0], a1[1], a1[2], a1[3], aAddr + aOff + kb + (uint32_t)(16 * PADK * 2));
            uint32_t b[8][2];
#pragma unroll
            for (int nt = 0; nt < 4; nt++) {
                uint32_t r0r, r1r, r2r, r3r;
                LDSM4(r0r, r1r, r2r, r3r,
                      bAddr + wOff + kb + (uint32_t)(nt * 16 * PADK * 2));
                b[nt * 2][0] = r0r; b[nt * 2][1] = r1r;
                b[nt * 2 + 1][0] = r2r; b[nt * 2 + 1][1] = r3r;
            }
#pragma unroll
            for (int f = 0; f < 8; f++) {
                MMA16816(acc[0][f], a0, b[f][0], b[f][1]);
                MMA16816(acc[1][f], a1, b[f][0], b[f][1]);
            }
        }
    }

    // epilogue: direct stores (float2 per fragment row)
#pragma unroll
    for (int mt = 0; mt < 2; mt++) {
        int ra = r0 + wm * 32 + mt * 16 + (lane >> 2);
        int rb = ra + 8;
#pragma unroll
        for (int f = 0; f < 8; f++) {
            int c = wn * 64 + f * 8 + (lane & 3) * 2;
            if (ra < nrows) *(float2*)(Cb + (size_t)ra * CH + c) =
                make_float2(acc[mt][f][0], acc[mt][f][1]);
            if (rb < nrows) *(float2*)(Cb + (size_t)rb * CH + c) =
                make_float2(acc[mt][f][2], acc[mt][f][3]);
        }
    }
}

// ---------------- weight convert + transpose: Wt[n][k] = W[k][n], bf16 hi/lo ----
// slab mapping: grpS==0 -> dst slab = y; else slab = (y/grpS)*grpStride + add + y%grpS
__global__ void conv_w(const float* __restrict__ src, __nv_bfloat16* __restrict__ dhi,
                       __nv_bfloat16* __restrict__ dlo, int grpS, int grpStride, int add)
{
    int y = blockIdx.y;
    int slab = (grpS == 0) ? y : (y / grpS) * grpStride + add + (y % grpS);
    int t = blockIdx.x * 256 + threadIdx.x;   // 0..16383
    int n = t >> 7, k = t & 127;
    float v = src[(size_t)y * (CH * CH) + k * CH + n];
    __nv_bfloat16 h = __float2bfloat16_rn(v);
    float l = v - __bfloat162float(h);
    dhi[(size_t)slab * (CH * CH) + t] = h;
    dlo[(size_t)slab * (CH * CH) + t] = __float2bfloat16_rn(l);
}

// ---------------- hi/lo split write helper --------------------------------------
__device__ __forceinline__ void write_hl(__nv_bfloat16* Hhi, __nv_bfloat16* Hlo,
                                         size_t idx2, float4 y)
{
    __nv_bfloat162 h01 = __floats2bfloat162_rn(y.x, y.y);
    __nv_bfloat162 h23 = __floats2bfloat162_rn(y.z, y.w);
    float lx = y.x - __bfloat162float(__low2bfloat16(h01));
    float ly = y.y - __bfloat162float(__high2bfloat16(h01));
    float lz = y.z - __bfloat162float(__low2bfloat16(h23));
    float lw = y.w - __bfloat162float(__high2bfloat16(h23));
    ((__nv_bfloat162*)Hhi)[idx2 + 0] = h01;
    ((__nv_bfloat162*)Hhi)[idx2 + 1] = h23;
    ((__nv_bfloat162*)Hlo)[idx2 + 0] = __floats2bfloat162_rn(lx, ly);
    ((__nv_bfloat162*)Hlo)[idx2 + 1] = __floats2bfloat162_rn(lz, lw);
}

// ---------------- dual scatter: T[u,:] += M[slab*N + v,:] -----------------------
// gw < half: edges from (U1,V1); else (U2,V2). msg slab = gw / Eper (global).
__global__ void scatter_dual(const float* __restrict__ M, float* __restrict__ T,
                             const int* __restrict__ U1, const int* __restrict__ V1,
                             const int* __restrict__ U2, const int* __restrict__ V2,
                             int half, int Eper, int ne, int N)
{
    int gw   = (int)((blockIdx.x * (unsigned)blockDim.x + threadIdx.x) >> 5);
    int lane = threadIdx.x & 31;
    if (gw >= ne) return;
    bool first = gw < half;
    int idx = first ? gw : gw - half;
    int u = first ? __ldg(U1 + idx) : __ldg(U2 + idx);
    int v = first ? __ldg(V1 + idx) : __ldg(V2 + idx);
    int slab = gw / Eper;
    float4 val = *(const float4*)(M + ((size_t)slab * N + v) * CH + lane * 4);
    float* dst = T + (size_t)u * CH + lane * 4;
    asm volatile("red.global.add.v4.f32 [%0], {%1, %2, %3, %4};"
                 :: "l"(dst), "f"(val.x), "f"(val.y), "f"(val.z), "f"(val.w) : "memory");
}

// ---------------- GroupNorm kernels (one warp per row) --------------------------
__device__ __forceinline__ void warp_red2(float& a, float& b)
{
#pragma unroll
    for (int o = 16; o; o >>= 1) {
        a += __shfl_xor_sync(0xffffffffu, a, o);
        b += __shfl_xor_sync(0xffffffffu, b, o);
    }
}

// Hhi/Hlo = split(relu(GN(X)*g + b))
__global__ void gn_relu_hl(const float* __restrict__ X, const float* __restrict__ G,
                           const float* __restrict__ Bv,
                           __nv_bfloat16* __restrict__ Hhi, __nv_bfloat16* __restrict__ Hlo, int n)
{
    int row  = (int)((blockIdx.x * (unsigned)blockDim.x + threadIdx.x) >> 5);
    int lane = threadIdx.x & 31;
    if (row >= n) return;
    float4 x = *(const float4*)(X + (size_t)row * CH + lane * 4);
    float s = x.x + x.y + x.z + x.w;
    float q = x.x * x.x + x.y * x.y + x.z * x.z + x.w * x.w;
    warp_red2(s, q);
    float mu = s * (1.f / CH);
    float rs = rsqrtf(q * (1.f / CH) - mu * mu + GN_EPS);
    float4 g = *(const float4*)(G + lane * 4);
    float4 b = *(const float4*)(Bv + lane * 4);
    float4 y;
    y.x = fmaxf((x.x - mu) * rs * g.x + b.x, 0.f);
    y.y = fmaxf((x.y - mu) * rs * g.y + b.y, 0.f);
    y.z = fmaxf((x.z - mu) * rs * g.z + b.z, 0.f);
    y.w = fmaxf((x.w - mu) * rs * g.w + b.w, 0.f);
    write_hl(Hhi, Hlo, ((size_t)row * 32 + lane) * 2, y);
}

// y = relu(GN(X)*g + b + ID); ID = y; Hhi/Hlo = split(y); optional OUT = y
__global__ void gn_res_hl(const float* __restrict__ X, const float* __restrict__ G,
                          const float* __restrict__ Bv, float* __restrict__ ID,
                          __nv_bfloat16* __restrict__ Hhi, __nv_bfloat16* __restrict__ Hlo,
                          float* __restrict__ OUT, int n)
{
    int row  = (int)((blockIdx.x * (unsigned)blockDim.x + threadIdx.x) >> 5);
    int lane = threadIdx.x & 31;
    if (row >= n) return;
    size_t off = (size_t)row * CH + lane * 4;
    float4 x = *(const float4*)(X + off);
    float s = x.x + x.y + x.z + x.w;
    float q = x.x * x.x + x.y * x.y + x.z * x.z + x.w * x.w;
    warp_red2(s, q);
    float mu = s * (1.f / CH);
    float rs = rsqrtf(q * (1.f / CH) - mu * mu + GN_EPS);
    float4 g  = *(const float4*)(G + lane * 4);
    float4 b  = *(const float4*)(Bv + lane * 4);
    float4 id = *(const float4*)(ID + off);
    float4 y;
    y.x = fmaxf((x.x - mu) * rs * g.x + b.x + id.x, 0.f);
    y.y = fmaxf((x.y - mu) * rs * g.y + b.y + id.y, 0.f);
    y.z = fmaxf((x.z - mu) * rs * g.z + b.z + id.z, 0.f);
    y.w = fmaxf((x.w - mu) * rs * g.w + b.w + id.w, 0.f);
    *(float4*)(ID + off) = y;
    if (OUT) *(float4*)(OUT + off) = y;
    write_hl(Hhi, Hlo, ((size_t)row * 32 + lane) * 2, y);
}

// y = relu(GN(X1)*g1+b1 + GN(X2)*g2+b2); IDN = y; Hhi/Hlo = split(y)
__global__ void gn_combine_hl(const float* __restrict__ X1, const float* __restrict__ X2,
                              const float* __restrict__ G1, const float* __restrict__ B1,
                              const float* __restrict__ G2, const float* __restrict__ B2,
                              float* __restrict__ IDN,
                              __nv_bfloat16* __restrict__ Hhi, __nv_bfloat16* __restrict__ Hlo, int n)
{
    int row  = (int)((blockIdx.x * (unsigned)blockDim.x + threadIdx.x) >> 5);
    int lane = threadIdx.x & 31;
    if (row >= n) return;
    size_t off = (size_t)row * CH + lane * 4;
    float4 a = *(const float4*)(X1 + off);
    float4 c = *(const float4*)(X2 + off);
    float s1 = a.x + a.y + a.z + a.w;
    float q1 = a.x * a.x + a.y * a.y + a.z * a.z + a.w * a.w;
    float s2 = c.x + c.y + c.z + c.w;
    float q2 = c.x * c.x + c.y * c.y + c.z * c.z + c.w * c.w;
    warp_red2(s1, q1);
    warp_red2(s2, q2);
    float mu1 = s1 * (1.f / CH);
    float rs1 = rsqrtf(q1 * (1.f / CH) - mu1 * mu1 + GN_EPS);
    float mu2 = s2 * (1.f / CH);
    float rs2 = rsqrtf(q2 * (1.f / CH) - mu2 * mu2 + GN_EPS);
    float4 g1 = *(const float4*)(G1 + lane * 4);
    float4 b1 = *(const float4*)(B1 + lane * 4);
    float4 g2 = *(const float4*)(G2 + lane * 4);
    float4 b2 = *(const float4*)(B2 + lane * 4);
    float4 y;
    y.x = fmaxf((a.x - mu1) * rs1 * g1.x + b1.x + (c.x - mu2) * rs2 * g2.x + b2.x, 0.f);
    y.y = fmaxf((a.y - mu1) * rs1 * g1.y + b1.y + (c.y - mu2) * rs2 * g2.y + b2.y, 0.f);
    y.z = fmaxf((a.z - mu1) * rs1 * g1.z + b1.z + (c.z - mu2) * rs2 * g2.z + b2.z, 0.f);
    y.w = fmaxf((a.w - mu1) * rs1 * g1.w + b1.w + (c.w - mu2) * rs2 * g2.w + b2.w, 0.f);
    *(float4*)(IDN + off) = y;
    write_hl(Hhi, Hlo, ((size_t)row * 32 + lane) * 2, y);
}

// H1 = relu(ctrs@cw0 + cb0), H2 = relu(feats@fw0 + fb0) -> hi/lo pairs
__global__ void input_mlp0_hl(const float* __restrict__ ctrs, const float* __restrict__ feats,
                              const float* __restrict__ cw0, const float* __restrict__ cb0,
                              const float* __restrict__ fw0, const float* __restrict__ fb0,
                              __nv_bfloat16* __restrict__ H1h, __nv_bfloat16* __restrict__ H1l,
                              __nv_bfloat16* __restrict__ H2h, __nv_bfloat16* __restrict__ H2l, int n)
{
    int row  = (int)((blockIdx.x * (unsigned)blockDim.x + threadIdx.x) >> 5);
    int lane = threadIdx.x & 31;
    if (row >= n) return;
    float c0 = __ldg(ctrs + (size_t)row * 2 + 0);
    float c1 = __ldg(ctrs + (size_t)row * 2 + 1);
    float e0 = __ldg(feats + (size_t)row * 2 + 0);
    float e1 = __ldg(feats + (size_t)row * 2 + 1);
    size_t idx2 = ((size_t)row * 32 + lane) * 2;

    float4 wa = *(const float4*)(cw0 + lane * 4);
    float4 wb = *(const float4*)(cw0 + CH + lane * 4);
    float4 bb = *(const float4*)(cb0 + lane * 4);
    float4 h;
    h.x = fmaxf(c0 * wa.x + c1 * wb.x + bb.x, 0.f);
    h.y = fmaxf(c0 * wa.y + c1 * wb.y + bb.y, 0.f);
    h.z = fmaxf(c0 * wa.z + c1 * wb.z + bb.z, 0.f);
    h.w = fmaxf(c0 * wa.w + c1 * wb.w + bb.w, 0.f);
    write_hl(H1h, H1l, idx2, h);

    wa = *(const float4*)(fw0 + lane * 4);
    wb = *(const float4*)(fw0 + CH + lane * 4);
    bb = *(const float4*)(fb0 + lane * 4);
    h.x = fmaxf(e0 * wa.x + e1 * wb.x + bb.x, 0.f);
    h.y = fmaxf(e0 * wa.y + e1 * wb.y + bb.y, 0.f);
    h.z = fmaxf(e0 * wa.z + e1 * wb.z + bb.z, 0.f);
    h.w = fmaxf(e0 * wa.w + e1 * wb.w + bb.w, 0.f);
    write_hl(H2h, H2l, idx2, h);
}

// ---------------- orchestration -------------------------------------------------
extern "C" void kernel_launch(void* const* d_in, const int* in_sizes, int n_in,
                              void* d_out, int out_size)
{
    const float* ctrs   = (const float*)d_in[0];
    const float* feats  = (const float*)d_in[1];
    const int*   pre_u  = (const int*)d_in[2];
    const int*   pre_v  = (const int*)d_in[3];
    const int*   suc_u  = (const int*)d_in[4];
    const int*   suc_v  = (const int*)d_in[5];
    const int*   left_u = (const int*)d_in[6];
    const int*   left_v = (const int*)d_in[7];
    const int*   right_u= (const int*)d_in[8];
    const int*   right_v= (const int*)d_in[9];
    const float* ic_w0  = (const float*)d_in[10];
    const float* ic_b0  = (const float*)d_in[11];
    const float* ic_w1  = (const float*)d_in[12];
    const float* ic_g   = (const float*)d_in[13];
    const float* ic_bt  = (const float*)d_in[14];
    const float* if_w0  = (const float*)d_in[15];
    const float* if_b0  = (const float*)d_in[16];
    const float* if_w1  = (const float*)d_in[17];
    const float* if_g   = (const float*)d_in[18];
    const float* if_bt  = (const float*)d_in[19];
    const float* ctr_w  = (const float*)d_in[20];
    const float* pre_w  = (const float*)d_in[21];
    const float* suc_w  = (const float*)d_in[22];
    const float* left_w = (const float*)d_in[23];
    const float* right_w= (const float*)d_in[24];
    const float* norm_g = (const float*)d_in[25];
    const float* norm_b = (const float*)d_in[26];
    const float* ctr2_w = (const float*)d_in[27];
    const float* ctr2_g = (const float*)d_in[28];
    const float* ctr2_b = (const float*)d_in[29];

    const int N   = in_sizes[0] / 2;
    const int EL  = in_sizes[6];
    const int BCC = in_sizes[20];              // B*C*C
    const int nB  = BCC / (CH * CH);
    const int S   = in_sizes[21] / BCC;
    const int E   = in_sizes[2] / S;

    float *idn, *tmp, *msg;
    __nv_bfloat16 *a0h, *a0l, *a1h, *a1l, *whi, *wlo;
    cudaGetSymbolAddress((void**)&idn, g_idn);
    cudaGetSymbolAddress((void**)&tmp, g_tmp);
    cudaGetSymbolAddress((void**)&msg, g_msg);
    cudaGetSymbolAddress((void**)&a0h, g_a0h);
    cudaGetSymbolAddress((void**)&a0l, g_a0l);
    cudaGetSymbolAddress((void**)&a1h, g_a1h);
    cudaGetSymbolAddress((void**)&a1l, g_a1l);
    cudaGetSymbolAddress((void**)&whi, g_whi);
    cudaGetSymbolAddress((void**)&wlo, g_wlo);

    cudaFuncSetAttribute(gemm_tc, cudaFuncAttributeMaxDynamicSharedMemorySize, GEMM_SMEM);

    const size_t cc = (size_t)CH * CH;
    // slot layout: [ic][if][ctr x nB][presuc: nB groups of 2S][lr: nB groups of 2][ctr2 x nB]
    const int slot_ic   = 0;
    const int slot_if   = 1;
    const int slot_ctr  = 2;
    const int slot_ps   = slot_ctr + nB;
    const int slot_lr   = slot_ps + nB * 2 * S;
    const int slot_ctr2 = slot_lr + nB * 2;

    // weight conversion (transpose + bf16 hi/lo)
    conv_w<<<dim3(64, 1), 256>>>(ic_w1, whi + (size_t)slot_ic * cc, wlo + (size_t)slot_ic * cc, 0, 0, 0);
    conv_w<<<dim3(64, 1), 256>>>(if_w1, whi + (size_t)slot_if * cc, wlo + (size_t)slot_if * cc, 0, 0, 0);
    conv_w<<<dim3(64, nB), 256>>>(ctr_w, whi + (size_t)slot_ctr * cc, wlo + (size_t)slot_ctr * cc, 0, 0, 0);
    // pre: group of S -> stride 2S, add 0; suc: add S
    conv_w<<<dim3(64, nB * S), 256>>>(pre_w, whi + (size_t)slot_ps * cc, wlo + (size_t)slot_ps * cc, S, 2 * S, 0);
    conv_w<<<dim3(64, nB * S), 256>>>(suc_w, whi + (size_t)slot_ps * cc, wlo + (size_t)slot_ps * cc, S, 2 * S, S);
    // left: group of 1 -> stride 2, add 0; right: add 1
    conv_w<<<dim3(64, nB), 256>>>(left_w,  whi + (size_t)slot_lr * cc, wlo + (size_t)slot_lr * cc, 1, 2, 0);
    conv_w<<<dim3(64, nB), 256>>>(right_w, whi + (size_t)slot_lr * cc, wlo + (size_t)slot_lr * cc, 1, 2, 1);
    conv_w<<<dim3(64, nB), 256>>>(ctr2_w, whi + (size_t)slot_ctr2 * cc, wlo + (size_t)slot_ctr2 * cc, 0, 0, 0);

    const int gX     = (N + 127) / 128;
    const int rwGrid = (N * 32 + 255) / 256;
    const int psGrid = (2 * S * E * 32 + 255) / 256;
    const int lrGrid = (2 * EL * 32 + 255) / 256;

    // ---- input stage ----
    input_mlp0_hl<<<rwGrid, 256>>>(ctrs, feats, ic_w0, ic_b0, if_w0, if_b0,
                                   a0h, a0l, a1h, a1l, N);
    gemm_tc<<<dim3(gX, 1), 256, GEMM_SMEM>>>(a0h, a0l,
        whi + (size_t)slot_ic * cc, wlo + (size_t)slot_ic * cc, tmp, N);
    gemm_tc<<<dim3(gX, 1), 256, GEMM_SMEM>>>(a1h, a1l,
        whi + (size_t)slot_if * cc, wlo + (size_t)slot_if * cc, msg, N);
    gn_combine_hl<<<rwGrid, 256>>>(tmp, msg, ic_g, ic_bt, if_g, if_bt, idn, a0h, a0l, N);

    // ---- fusion blocks ----
    for (int i = 0; i < nB; i++) {
        gemm_tc<<<dim3(gX, 1), 256, GEMM_SMEM>>>(a0h, a0l,
            whi + (size_t)(slot_ctr + i) * cc, wlo + (size_t)(slot_ctr + i) * cc, tmp, N);

        // pre(S) + suc(S) batched: y = 2S slabs of msg
        gemm_tc<<<dim3(gX, 2 * S), 256, GEMM_SMEM>>>(a0h, a0l,
            whi + (size_t)(slot_ps + i * 2 * S) * cc, wlo + (size_t)(slot_ps + i * 2 * S) * cc, msg, N);
        scatter_dual<<<psGrid, 256>>>(msg, tmp, pre_u, pre_v, suc_u, suc_v,
                                      S * E, E, 2 * S * E, N);

        // left + right batched: y = 2
        gemm_tc<<<dim3(gX, 2), 256, GEMM_SMEM>>>(a0h, a0l,
            whi + (size_t)(slot_lr + i * 2) * cc, wlo + (size_t)(slot_lr + i * 2) * cc, msg, N);
        scatter_dual<<<lrGrid, 256>>>(msg, tmp, left_u, left_v, right_u, right_v,
                                      EL, EL, 2 * EL, N);

        gn_relu_hl<<<rwGrid, 256>>>(tmp, norm_g + (size_t)i * CH, norm_b + (size_t)i * CH,
                                    a1h, a1l, N);
        gemm_tc<<<dim3(gX, 1), 256, GEMM_SMEM>>>(a1h, a1l,
            whi + (size_t)(slot_ctr2 + i) * cc, wlo + (size_t)(slot_ctr2 + i) * cc, msg, N);
        gn_res_hl<<<rwGrid, 256>>>(msg, ctr2_g + (size_t)i * CH, ctr2_b + (size_t)i * CH,
                                   idn, a0h, a0l,
                                   (i == nB - 1) ? (float*)d_out : (float*)nullptr, N);
    }
}

// round 8
// speedup vs baseline: 3.2493x; 1.1613x over previous
#include <cuda_runtime.h>
#include <cuda_bf16.h>
#include <cstdint>
#include <cstddef>

#define CH 128
#define MAXN 131072
#define MAXS 6
#define GN_EPS 1e-5f

// ---------------- static scratch (no runtime alloc) ----------------------------
__device__ float g_idn [(size_t)MAXN * CH];                       // feat (f32)
__device__ float g_tmp [(size_t)MAXN * CH];
__device__ float g_msg [(size_t)(2 * MAXS + 2) * MAXN * CH];      // 14 slabs
#define MAXW 128
__device__ __nv_bfloat16 g_whi[(size_t)MAXW * CH * CH];
__device__ __nv_bfloat16 g_wlo[(size_t)MAXW * CH * CH];

// ---------------- helpers -------------------------------------------------------
__device__ __forceinline__ uint32_t smem_u32(const void* p) {
    uint32_t a;
    asm("{ .reg .u64 t; cvta.to.shared.u64 t, %1; cvt.u32.u64 %0, t; }" : "=r"(a) : "l"(p));
    return a;
}

#define LDSM4(d0, d1, d2, d3, addr) \
    asm volatile("ldmatrix.sync.aligned.m8n8.x4.shared.b16 {%0,%1,%2,%3}, [%4];" \
                 : "=r"(d0), "=r"(d1), "=r"(d2), "=r"(d3) : "r"(addr))

#define MMA16816(c, a, b0, b1) \
    asm volatile("mma.sync.aligned.m16n8k16.row.col.f32.bf16.bf16.f32 " \
                 "{%0,%1,%2,%3}, {%4,%5,%6,%7}, {%8,%9}, {%0,%1,%2,%3};" \
                 : "+f"((c)[0]), "+f"((c)[1]), "+f"((c)[2]), "+f"((c)[3]) \
                 : "r"((a)[0]), "r"((a)[1]), "r"((a)[2]), "r"((a)[3]), "r"(b0), "r"(b1))

#define CP_ASYNC16(dst, src) \
    asm volatile("cp.async.cg.shared.global [%0], [%1], 16;" :: "r"(dst), "l"(src))
#define CP_COMMIT() asm volatile("cp.async.commit_group;" ::: "memory")
#define CP_WAIT0()  asm volatile("cp.async.wait_group 0;" ::: "memory")

#define PADK 136                               // bf16 elems per row (128 + 8 pad)
#define TILE_E (128 * PADK)                    // bf16 elems per tile
#define TILE_BYTES (TILE_E * 2)                // 34816 bytes
#define MS_SMEM (6 * TILE_BYTES)               // A(h,l) + 2 W bufs(h,l) = 208896
#define F_SMEM  (4 * TILE_BYTES)               // A(h,l) + W(h,l) = 139264

__device__ __forceinline__ void split_store(__nv_bfloat16* sh, __nv_bfloat16* sl,
                                            int off, float4 v)
{
    __nv_bfloat162 h01 = __floats2bfloat162_rn(v.x, v.y);
    __nv_bfloat162 h23 = __floats2bfloat162_rn(v.z, v.w);
    float lx = v.x - __bfloat162float(__low2bfloat16(h01));
    float ly = v.y - __bfloat162float(__high2bfloat16(h01));
    float lz = v.z - __bfloat162float(__low2bfloat16(h23));
    float lw = v.w - __bfloat162float(__high2bfloat16(h23));
    *(__nv_bfloat162*)(sh + off)     = h01;
    *(__nv_bfloat162*)(sh + off + 2) = h23;
    *(__nv_bfloat162*)(sl + off)     = __floats2bfloat162_rn(lx, ly);
    *(__nv_bfloat162*)(sl + off + 2) = __floats2bfloat162_rn(lz, lw);
}

__device__ __forceinline__ void warp_red2(float& a, float& b)
{
#pragma unroll
    for (int o = 16; o; o >>= 1) {
        a += __shfl_xor_sync(0xffffffffu, a, o);
        b += __shfl_xor_sync(0xffffffffu, b, o);
    }
}

// issue cp.async for W slab s into buffer buf (tiles 2+2*buf, 3+2*buf)
__device__ __forceinline__ void issue_w(uint32_t sbase, int tid,
                                        const __nv_bfloat16* Whb, const __nv_bfloat16* Wlb,
                                        int s, int buf)
{
    const char* srcH = (const char*)(Whb + (size_t)s * (CH * CH));
    const char* srcL = (const char*)(Wlb + (size_t)s * (CH * CH));
    uint32_t dstH = sbase + (uint32_t)((2 + 2 * buf) * TILE_BYTES);
    uint32_t dstL = dstH + (uint32_t)TILE_BYTES;
#pragma unroll
    for (int it = 0; it < 8; it++) {
        int ch = tid + it * 256;                 // 0..2047
        int row = ch >> 4, c = ch & 15;
        uint32_t off = (uint32_t)((row * PADK + c * 8) * 2);
        CP_ASYNC16(dstH + off, srcH + (size_t)ch * 16);
        CP_ASYNC16(dstL + off, srcL + (size_t)ch * 16);
    }
}

// ---------------- multi-slab GEMM: loads A once, loops W slabs -------------------
// dst for slab 0 = dst0; slab s>=1 -> dstR + (s-1)*nrows*CH
__global__ __launch_bounds__(256, 1)
void gemm_ms(const float* __restrict__ A,
             const __nv_bfloat16* __restrict__ Whb, const __nv_bfloat16* __restrict__ Wlb,
             float* __restrict__ dst0, float* __restrict__ dstR,
             int nslabs, int nrows)
{
    extern __shared__ __nv_bfloat16 sm[];
    __nv_bfloat16* sAh = sm;
    __nv_bfloat16* sAl = sm + TILE_E;

    const int tid  = threadIdx.x;
    const int lane = tid & 31;
    const int wid  = tid >> 5;
    const int wm   = wid >> 1;
    const int wn   = wid & 1;
    const int r0   = blockIdx.x * 128;
    const uint32_t sbase = smem_u32(sm);

    issue_w(sbase, tid, Whb, Wlb, 0, 0);
    CP_COMMIT();

    // A load + hi/lo split (f32 -> bf16 pair), once
#pragma unroll
    for (int it = 0; it < 16; it++) {
        int idx = tid + it * 256;               // 0..4095 float4 chunks
        int row = idx >> 5, c4 = idx & 31;
        bool ok = (r0 + row) < nrows;
        float4 v = ok ? *(const float4*)(A + (size_t)(r0 + row) * CH + c4 * 4)
                      : make_float4(0.f, 0.f, 0.f, 0.f);
        split_store(sAh, sAl, row * PADK + c4 * 4, v);
    }
    CP_WAIT0();
    __syncthreads();

    const uint32_t aAddr = sbase +
        (uint32_t)(((wm * 32 + (lane & 15)) * PADK + (lane >> 4) * 8) * 2);
    const uint32_t bOffL = (uint32_t)(((wn * 64 + (lane & 7) + ((lane >> 4) << 3)) * PADK +
                                      ((lane >> 3) & 1) * 8) * 2);

    for (int s = 0; s < nslabs; s++) {
        const int buf = s & 1;
        if (s + 1 < nslabs) { issue_w(sbase, tid, Whb, Wlb, s + 1, buf ^ 1); CP_COMMIT(); }

        const uint32_t bBase = sbase + (uint32_t)((2 + 2 * buf) * TILE_BYTES) + bOffL;

        float acc[2][8][4];
#pragma unroll
        for (int mt = 0; mt < 2; mt++)
#pragma unroll
            for (int f = 0; f < 8; f++)
#pragma unroll
                for (int i = 0; i < 4; i++) acc[mt][f][i] = 0.f;

#pragma unroll
        for (int term = 0; term < 3; term++) {
            const uint32_t aOff = (term == 1) ? (uint32_t)TILE_BYTES : 0u;
            const uint32_t wOff = (term == 2) ? (uint32_t)TILE_BYTES : 0u;
#pragma unroll
            for (int ks = 0; ks < 8; ks++) {
                const uint32_t kb = ks * 32;
                uint32_t a0[4], a1[4];
                LDSM4(a0[0], a0[1], a0[2], a0[3], aAddr + aOff + kb);
                LDSM4(a1[0], a1[1], a1[2], a1[3],
                      aAddr + aOff + kb + (uint32_t)(16 * PADK * 2));
                uint32_t b[8][2];
#pragma unroll
                for (int nt = 0; nt < 4; nt++) {
                    uint32_t q0, q1, q2, q3;
                    LDSM4(q0, q1, q2, q3, bBase + wOff + kb + (uint32_t)(nt * 16 * PADK * 2));
                    b[nt * 2][0] = q0; b[nt * 2][1] = q1;
                    b[nt * 2 + 1][0] = q2; b[nt * 2 + 1][1] = q3;
                }
#pragma unroll
                for (int f = 0; f < 8; f++) {
                    MMA16816(acc[0][f], a0, b[f][0], b[f][1]);
                    MMA16816(acc[1][f], a1, b[f][0], b[f][1]);
                }
            }
        }

        float* Cb = (s == 0) ? dst0 : dstR + (size_t)(s - 1) * nrows * CH;
#pragma unroll
        for (int mt = 0; mt < 2; mt++) {
            int ra = r0 + wm * 32 + mt * 16 + (lane >> 2);
            int rb = ra + 8;
#pragma unroll
            for (int f = 0; f < 8; f++) {
                int c = wn * 64 + f * 8 + (lane & 3) * 2;
                if (ra < nrows) *(float2*)(Cb + (size_t)ra * CH + c) =
                    make_float2(acc[mt][f][0], acc[mt][f][1]);
                if (rb < nrows) *(float2*)(Cb + (size_t)rb * CH + c) =
                    make_float2(acc[mt][f][2], acc[mt][f][3]);
            }
        }

        if (s + 1 < nslabs) CP_WAIT0();
        __syncthreads();
    }
}

// ---------------- fused block tail: A=relu(GN(tmp)), C=GN(A@W)+idn, relu --------
__global__ __launch_bounds__(256, 1)
void gemm_ctr2_fused(const float* __restrict__ T,
                     const float* __restrict__ Gn, const float* __restrict__ Bn,
                     const __nv_bfloat16* __restrict__ Wh, const __nv_bfloat16* __restrict__ Wl,
                     const float* __restrict__ G2, const float* __restrict__ B2,
                     float* __restrict__ IDN, float* __restrict__ OUT, int nrows)
{
    extern __shared__ __nv_bfloat16 sm[];
    __nv_bfloat16* sAh = sm;
    __nv_bfloat16* sAl = sm + TILE_E;
    __nv_bfloat16* sWh = sm + 2 * TILE_E;
    __nv_bfloat16* sWl = sm + 3 * TILE_E;

    const int tid  = threadIdx.x;
    const int lane = tid & 31;
    const int wid  = tid >> 5;
    const int wm   = wid >> 1;
    const int wn   = wid & 1;
    const int r0   = blockIdx.x * 128;
    const uint32_t sbase = smem_u32(sm);

    // W load (single slab, plain)
    {
        const uint4* gWh = (const uint4*)Wh;
        const uint4* gWl = (const uint4*)Wl;
#pragma unroll
        for (int it = 0; it < 8; it++) {
            int ch = tid + it * 256;
            int row = ch >> 4, c = ch & 15;
            size_t doff = (size_t)row * PADK + c * 8;
            *(uint4*)(sWh + doff) = gWh[ch];
            *(uint4*)(sWl + doff) = gWl[ch];
        }
    }

    // A prologue: per-row GN(tmp) + relu, split to bf16 hi/lo in smem
    {
        float4 g = *(const float4*)(Gn + lane * 4);
        float4 b = *(const float4*)(Bn + lane * 4);
#pragma unroll 4
        for (int r = 0; r < 16; r++) {
            int lr  = wid * 16 + r;
            int row = r0 + lr;
            float4 x = (row < nrows) ? *(const float4*)(T + (size_t)row * CH + lane * 4)
                                     : make_float4(0.f, 0.f, 0.f, 0.f);
            float s = x.x + x.y + x.z + x.w;
            float q = x.x * x.x + x.y * x.y + x.z * x.z + x.w * x.w;
            warp_red2(s, q);
            float mu = s * (1.f / CH);
            float rs = rsqrtf(q * (1.f / CH) - mu * mu + GN_EPS);
            float4 y;
            y.x = fmaxf((x.x - mu) * rs * g.x + b.x, 0.f);
            y.y = fmaxf((x.y - mu) * rs * g.y + b.y, 0.f);
            y.z = fmaxf((x.z - mu) * rs * g.z + b.z, 0.f);
            y.w = fmaxf((x.w - mu) * rs * g.w + b.w, 0.f);
            split_store(sAh, sAl, lr * PADK + lane * 4, y);
        }
    }
    __syncthreads();

    const uint32_t aAddr = sbase +
        (uint32_t)(((wm * 32 + (lane & 15)) * PADK + (lane >> 4) * 8) * 2);
    const uint32_t bBase = sbase + (uint32_t)(2 * TILE_BYTES) +
        (uint32_t)(((wn * 64 + (lane & 7) + ((lane >> 4) << 3)) * PADK +
                    ((lane >> 3) & 1) * 8) * 2);

    float acc[2][8][4];
#pragma unroll
    for (int mt = 0; mt < 2; mt++)
#pragma unroll
        for (int f = 0; f < 8; f++)
#pragma unroll
            for (int i = 0; i < 4; i++) acc[mt][f][i] = 0.f;

#pragma unroll
    for (int term = 0; term < 3; term++) {
        const uint32_t aOff = (term == 1) ? (uint32_t)TILE_BYTES : 0u;
        const uint32_t wOff = (term == 2) ? (uint32_t)TILE_BYTES : 0u;
#pragma unroll
        for (int ks = 0; ks < 8; ks++) {
            const uint32_t kb = ks * 32;
            uint32_t a0[4], a1[4];
            LDSM4(a0[0], a0[1], a0[2], a0[3], aAddr + aOff + kb);
            LDSM4(a1[0], a1[1], a1[2], a1[3],
                  aAddr + aOff + kb + (uint32_t)(16 * PADK * 2));
            uint32_t b[8][2];
#pragma unroll
            for (int nt = 0; nt < 4; nt++) {
                uint32_t q0, q1, q2, q3;
                LDSM4(q0, q1, q2, q3, bBase + wOff + kb + (uint32_t)(nt * 16 * PADK * 2));
                b[nt * 2][0] = q0; b[nt * 2][1] = q1;
                b[nt * 2 + 1][0] = q2; b[nt * 2 + 1][1] = q3;
            }
#pragma unroll
            for (int f = 0; f < 8; f++) {
                MMA16816(acc[0][f], a0, b[f][0], b[f][1]);
                MMA16816(acc[1][f], a1, b[f][0], b[f][1]);
            }
        }
    }
    __syncthreads();   // all warps done reading sW before staging over it

    // stage C tile to smem f32 [128][132]
    float* stage = (float*)(sm + 2 * TILE_E);
#pragma unroll
    for (int mt = 0; mt < 2; mt++) {
        int sr = wm * 32 + mt * 16 + (lane >> 2);
#pragma unroll
        for (int f = 0; f < 8; f++) {
            int sc = wn * 64 + f * 8 + (lane & 3) * 2;
            stage[sr * 132 + sc]           = acc[mt][f][0];
            stage[sr * 132 + sc + 1]       = acc[mt][f][1];
            stage[(sr + 8) * 132 + sc]     = acc[mt][f][2];
            stage[(sr + 8) * 132 + sc + 1] = acc[mt][f][3];
        }
    }
    __syncthreads();

    // epilogue: GN + residual + relu, write idn (and OUT on last block)
    {
        float4 g = *(const float4*)(G2 + lane * 4);
        float4 b = *(const float4*)(B2 + lane * 4);
#pragma unroll 4
        for (int r = 0; r < 16; r++) {
            int lr  = wid * 16 + r;
            int row = r0 + lr;
            if (row >= nrows) break;
            float4 x = *(const float4*)(stage + lr * 132 + lane * 4);
            float s = x.x + x.y + x.z + x.w;
            float q = x.x * x.x + x.y * x.y + x.z * x.z + x.w * x.w;
            warp_red2(s, q);
            float mu = s * (1.f / CH);
            float rs = rsqrtf(q * (1.f / CH) - mu * mu + GN_EPS);
            size_t off = (size_t)row * CH + lane * 4;
            float4 id = *(const float4*)(IDN + off);
            float4 y;
            y.x = fmaxf((x.x - mu) * rs * g.x + b.x + id.x, 0.f);
            y.y = fmaxf((x.y - mu) * rs * g.y + b.y + id.y, 0.f);
            y.z = fmaxf((x.z - mu) * rs * g.z + b.z + id.z, 0.f);
            y.w = fmaxf((x.w - mu) * rs * g.w + b.w + id.w, 0.f);
            *(float4*)(IDN + off) = y;
            if (OUT) *(float4*)(OUT + off) = y;
        }
    }
}

// ---------------- weight convert + transpose ------------------------------------
// slab = (grpS==0) ? y : (y/grpS)*grpStride + add + y%grpS
__global__ void conv_w(const float* __restrict__ src, __nv_bfloat16* __restrict__ dhi,
                       __nv_bfloat16* __restrict__ dlo, int grpS, int grpStride, int add)
{
    int y = blockIdx.y;
    int slab = (grpS == 0) ? y : (y / grpS) * grpStride + add + (y % grpS);
    int t = blockIdx.x * 256 + threadIdx.x;
    int n = t >> 7, k = t & 127;
    float v = src[(size_t)y * (CH * CH) + k * CH + n];
    __nv_bfloat16 h = __float2bfloat16_rn(v);
    float l = v - __bfloat162float(h);
    dhi[(size_t)slab * (CH * CH) + t] = h;
    dlo[(size_t)slab * (CH * CH) + t] = __float2bfloat16_rn(l);
}

// ---------------- dual scatter: T[u,:] += M[slab*N + v,:] -----------------------
__global__ void scatter_dual(const float* __restrict__ M, float* __restrict__ T,
                             const int* __restrict__ U1, const int* __restrict__ V1,
                             const int* __restrict__ U2, const int* __restrict__ V2,
                             int half, int Eper, int ne, int N)
{
    int gw   = (int)((blockIdx.x * (unsigned)blockDim.x + threadIdx.x) >> 5);
    int lane = threadIdx.x & 31;
    if (gw >= ne) return;
    bool first = gw < half;
    int idx = first ? gw : gw - half;
    int u = first ? __ldg(U1 + idx) : __ldg(U2 + idx);
    int v = first ? __ldg(V1 + idx) : __ldg(V2 + idx);
    int slab = gw / Eper;
    float4 val = *(const float4*)(M + ((size_t)slab * N + v) * CH + lane * 4);
    float* dst = T + (size_t)u * CH + lane * 4;
    asm volatile("red.global.add.v4.f32 [%0], {%1, %2, %3, %4};"
                 :: "l"(dst), "f"(val.x), "f"(val.y), "f"(val.z), "f"(val.w) : "memory");
}

// ---------------- input-stage small kernels -------------------------------------
__global__ void input_mlp0(const float* __restrict__ ctrs, const float* __restrict__ feats,
                           const float* __restrict__ cw0, const float* __restrict__ cb0,
                           const float* __restrict__ fw0, const float* __restrict__ fb0,
                           float* __restrict__ H1, float* __restrict__ H2, int n)
{
    int row  = (int)((blockIdx.x * (unsigned)blockDim.x + threadIdx.x) >> 5);
    int lane = threadIdx.x & 31;
    if (row >= n) return;
    float c0 = __ldg(ctrs + (size_t)row * 2 + 0);
    float c1 = __ldg(ctrs + (size_t)row * 2 + 1);
    float e0 = __ldg(feats + (size_t)row * 2 + 0);
    float e1 = __ldg(feats + (size_t)row * 2 + 1);
    size_t off = (size_t)row * CH + lane * 4;

    float4 wa = *(const float4*)(cw0 + lane * 4);
    float4 wb = *(const float4*)(cw0 + CH + lane * 4);
    float4 bb = *(const float4*)(cb0 + lane * 4);
    float4 h;
    h.x = fmaxf(c0 * wa.x + c1 * wb.x + bb.x, 0.f);
    h.y = fmaxf(c0 * wa.y + c1 * wb.y + bb.y, 0.f);
    h.z = fmaxf(c0 * wa.z + c1 * wb.z + bb.z, 0.f);
    h.w = fmaxf(c0 * wa.w + c1 * wb.w + bb.w, 0.f);
    *(float4*)(H1 + off) = h;

    wa = *(const float4*)(fw0 + lane * 4);
    wb = *(const float4*)(fw0 + CH + lane * 4);
    bb = *(const float4*)(fb0 + lane * 4);
    h.x = fmaxf(e0 * wa.x + e1 * wb.x + bb.x, 0.f);
    h.y = fmaxf(e0 * wa.y + e1 * wb.y + bb.y, 0.f);
    h.z = fmaxf(e0 * wa.z + e1 * wb.z + bb.z, 0.f);
    h.w = fmaxf(e0 * wa.w + e1 * wb.w + bb.w, 0.f);
    *(float4*)(H2 + off) = h;
}

// IDN = relu(GN(X1)*g1+b1 + GN(X2)*g2+b2)
__global__ void gn_combine(const float* __restrict__ X1, const float* __restrict__ X2,
                           const float* __restrict__ G1, const float* __restrict__ B1,
                           const float* __restrict__ G2, const float* __restrict__ B2,
                           float* __restrict__ IDN, int n)
{
    int row  = (int)((blockIdx.x * (unsigned)blockDim.x + threadIdx.x) >> 5);
    int lane = threadIdx.x & 31;
    if (row >= n) return;
    size_t off = (size_t)row * CH + lane * 4;
    float4 a = *(const float4*)(X1 + off);
    float4 c = *(const float4*)(X2 + off);
    float s1 = a.x + a.y + a.z + a.w;
    float q1 = a.x * a.x + a.y * a.y + a.z * a.z + a.w * a.w;
    float s2 = c.x + c.y + c.z + c.w;
    float q2 = c.x * c.x + c.y * c.y + c.z * c.z + c.w * c.w;
    warp_red2(s1, q1);
    warp_red2(s2, q2);
    float mu1 = s1 * (1.f / CH);
    float rs1 = rsqrtf(q1 * (1.f / CH) - mu1 * mu1 + GN_EPS);
    float mu2 = s2 * (1.f / CH);
    float rs2 = rsqrtf(q2 * (1.f / CH) - mu2 * mu2 + GN_EPS);
    float4 g1 = *(const float4*)(G1 + lane * 4);
    float4 b1 = *(const float4*)(B1 + lane * 4);
    float4 g2 = *(const float4*)(G2 + lane * 4);
    float4 b2 = *(const float4*)(B2 + lane * 4);
    float4 y;
    y.x = fmaxf((a.x - mu1) * rs1 * g1.x + b1.x + (c.x - mu2) * rs2 * g2.x + b2.x, 0.f);
    y.y = fmaxf((a.y - mu1) * rs1 * g1.y + b1.y + (c.y - mu2) * rs2 * g2.y + b2.y, 0.f);
    y.z = fmaxf((a.z - mu1) * rs1 * g1.z + b1.z + (c.z - mu2) * rs2 * g2.z + b2.z, 0.f);
    y.w = fmaxf((a.w - mu1) * rs1 * g1.w + b1.w + (c.w - mu2) * rs2 * g2.w + b2.w, 0.f);
    *(float4*)(IDN + off) = y;
}

// ---------------- orchestration -------------------------------------------------
extern "C" void kernel_launch(void* const* d_in, const int* in_sizes, int n_in,
                              void* d_out, int out_size)
{
    const float* ctrs   = (const float*)d_in[0];
    const float* feats  = (const float*)d_in[1];
    const int*   pre_u  = (const int*)d_in[2];
    const int*   pre_v  = (const int*)d_in[3];
    const int*   suc_u  = (const int*)d_in[4];
    const int*   suc_v  = (const int*)d_in[5];
    const int*   left_u = (const int*)d_in[6];
    const int*   left_v = (const int*)d_in[7];
    const int*   right_u= (const int*)d_in[8];
    const int*   right_v= (const int*)d_in[9];
    const float* ic_w0  = (const float*)d_in[10];
    const float* ic_b0  = (const float*)d_in[11];
    const float* ic_w1  = (const float*)d_in[12];
    const float* ic_g   = (const float*)d_in[13];
    const float* ic_bt  = (const float*)d_in[14];
    const float* if_w0  = (const float*)d_in[15];
    const float* if_b0  = (const float*)d_in[16];
    const float* if_w1  = (const float*)d_in[17];
    const float* if_g   = (const float*)d_in[18];
    const float* if_bt  = (const float*)d_in[19];
    const float* ctr_w  = (const float*)d_in[20];
    const float* pre_w  = (const float*)d_in[21];
    const float* suc_w  = (const float*)d_in[22];
    const float* left_w = (const float*)d_in[23];
    const float* right_w= (const float*)d_in[24];
    const float* norm_g = (const float*)d_in[25];
    const float* norm_b = (const float*)d_in[26];
    const float* ctr2_w = (const float*)d_in[27];
    const float* ctr2_g = (const float*)d_in[28];
    const float* ctr2_b = (const float*)d_in[29];

    const int N   = in_sizes[0] / 2;
    const int EL  = in_sizes[6];
    const int BCC = in_sizes[20];              // B*C*C
    const int nB  = BCC / (CH * CH);
    const int S   = in_sizes[21] / BCC;
    const int E   = in_sizes[2] / S;

    float *idn, *tmp, *msg;
    __nv_bfloat16 *whi, *wlo;
    cudaGetSymbolAddress((void**)&idn, g_idn);
    cudaGetSymbolAddress((void**)&tmp, g_tmp);
    cudaGetSymbolAddress((void**)&msg, g_msg);
    cudaGetSymbolAddress((void**)&whi, g_whi);
    cudaGetSymbolAddress((void**)&wlo, g_wlo);

    cudaFuncSetAttribute(gemm_ms, cudaFuncAttributeMaxDynamicSharedMemorySize, MS_SMEM);
    cudaFuncSetAttribute(gemm_ctr2_fused, cudaFuncAttributeMaxDynamicSharedMemorySize, F_SMEM);

    const size_t cc = (size_t)CH * CH;
    const int nps = 15;   // per-block GEMM slabs: ctr + S pre + S suc + left + right
    // slot layout: [ic=0][if=1][block i: base=2+15i {ctr, pre*S, suc*S, left, right}][ctr2: 2+15nB+i]
    const int slot_ctr2 = 2 + nps * nB;

    conv_w<<<dim3(64, 1), 256>>>(ic_w1, whi, wlo, 0, 0, 0);
    conv_w<<<dim3(64, 1), 256>>>(if_w1, whi, wlo, 1, 1, 1);
    conv_w<<<dim3(64, nB), 256>>>(ctr_w, whi, wlo, 1, nps, 2);
    conv_w<<<dim3(64, nB * S), 256>>>(pre_w, whi, wlo, S, nps, 3);
    conv_w<<<dim3(64, nB * S), 256>>>(suc_w, whi, wlo, S, nps, 3 + S);
    conv_w<<<dim3(64, nB), 256>>>(left_w,  whi, wlo, 1, nps, 3 + 2 * S);
    conv_w<<<dim3(64, nB), 256>>>(right_w, whi, wlo, 1, nps, 4 + 2 * S);
    conv_w<<<dim3(64, nB), 256>>>(ctr2_w, whi, wlo, 1, 1, slot_ctr2);

    const int gX     = (N + 127) / 128;
    const int rwGrid = (N * 32 + 255) / 256;
    const int psGrid = (2 * S * E * 32 + 255) / 256;
    const int lrGrid = (2 * EL * 32 + 255) / 256;

    // ---- input stage ----
    input_mlp0<<<rwGrid, 256>>>(ctrs, feats, ic_w0, ic_b0, if_w0, if_b0, tmp, idn, N);
    gemm_ms<<<gX, 256, MS_SMEM>>>(tmp, whi, wlo, msg, (float*)nullptr, 1, N);
    gemm_ms<<<gX, 256, MS_SMEM>>>(idn, whi + cc, wlo + cc,
                                  msg + (size_t)N * CH, (float*)nullptr, 1, N);
    gn_combine<<<rwGrid, 256>>>(msg, msg + (size_t)N * CH, ic_g, ic_bt, if_g, if_bt, idn, N);

    // ---- fusion blocks ----
    for (int i = 0; i < nB; i++) {
        const size_t wb = (size_t)(2 + nps * i) * cc;
        // all 15 GEMMs in one launch: slab0 -> tmp; slabs 1..14 -> msg slabs 0..13
        gemm_ms<<<gX, 256, MS_SMEM>>>(idn, whi + wb, wlo + wb, tmp, msg, nps, N);

        // pre (msg slabs 0..5) + suc (6..11)
        scatter_dual<<<psGrid, 256>>>(msg, tmp, pre_u, pre_v, suc_u, suc_v,
                                      S * E, E, 2 * S * E, N);
        // left (slab 12) + right (slab 13)
        scatter_dual<<<lrGrid, 256>>>(msg + (size_t)12 * N * CH, tmp,
                                      left_u, left_v, right_u, right_v,
                                      EL, EL, 2 * EL, N);

        const size_t w2 = (size_t)(slot_ctr2 + i) * cc;
        gemm_ctr2_fused<<<gX, 256, F_SMEM>>>(tmp,
            norm_g + (size_t)i * CH, norm_b + (size_t)i * CH,
            whi + w2, wlo + w2,
            ctr2_g + (size_t)i * CH, ctr2_b + (size_t)i * CH,
            idn, (i == nB - 1) ? (float*)d_out : (float*)nullptr, N);
    }
}